// round 13
// baseline (speedup 1.0000x reference)
#include <cuda_runtime.h>
#include <cuda_fp16.h>
#include <math.h>

#define NN 100000
#define EE 1600000
#define NB_SCAN 98        // ceil(NN/1024)
#define NTILES_G (EE / 128)

typedef unsigned long long u64;

// ---------------- packed f32x2 helpers (Blackwell) ----------------
__device__ __forceinline__ u64 pk2(float lo, float hi) {
    u64 r; asm("mov.b64 %0, {%1, %2};" : "=l"(r) : "f"(lo), "f"(hi)); return r;
}
__device__ __forceinline__ void upk2(u64 v, float& lo, float& hi) {
    asm("mov.b64 {%0, %1}, %2;" : "=f"(lo), "=f"(hi) : "l"(v));
}
__device__ __forceinline__ u64 ffma2(u64 a, u64 b, u64 c) {
    u64 d; asm("fma.rn.f32x2 %0, %1, %2, %3;" : "=l"(d) : "l"(a), "l"(b), "l"(c)); return d;
}

// ---------------- scratch (static device globals; no allocs) ----------------
__device__ __align__(16) float  g_gate[EE];
__device__ __align__(16) int    g_src[EE];
__device__ __align__(16) int    g_dst[EE];
__device__ __align__(16) int    g_off[EE];          // within-bucket offset (from gate atomics)
__device__ __align__(16) u64    g_csr[EE];          // hi: norm bits, lo: src
__device__ __align__(16) float  g_deg[NN];
__device__ __align__(16) float  g_dinv[NN];
__device__ __align__(16) int    g_cnt[NN];
__device__ __align__(16) int    g_tmp[NN];
__device__ __align__(16) int    g_rowptr[NN + 1];
__device__ __align__(16) int    g_bsum[NB_SCAN];
__device__ __align__(16) __half g_tu16[NN * 64];
__device__ __align__(16) __half g_tv16[NN * 64];
__device__ __align__(16) __half g_xw16[NN * 128];
__device__ __align__(16) float  g_x1[NN * 128];
__device__ int g_is32;

// ---------------- init (deg=1 self-loop, cnt=0) + dtype detect ----------------
__global__ void k_init(const long long* __restrict__ ei) {
    int i = blockIdx.x * 256 + threadIdx.x;
    if (i < NN) { g_deg[i] = 1.0f; g_cnt[i] = 0; }
    if (i == 0) {
        int bad = 0;
        for (int t = 0; t < 128; ++t) {
            long long v = ei[t];
            if (v < 0 || v >= (long long)NN) { bad = 1; break; }
        }
        g_is32 = bad;
    }
}

// ---------------- node_pre: warp per node, fp16 output, coalesced stores ----------------
__global__ __launch_bounds__(256) void k_node_pre(const float* __restrict__ motif,
                                                  const float* __restrict__ w1) {
    __shared__ __align__(16) float sW[32 * 64];
    for (int i = threadIdx.x; i < 2048; i += 256) sW[i] = w1[i];
    __syncthreads();

    int lane = threadIdx.x & 31;
    int warpId = (blockIdx.x * 256 + threadIdx.x) >> 5;
    int nWarps = (gridDim.x * 256) >> 5;
    int half = lane >> 4;              // 0: tu (W rows 0..15), 1: tv (rows 16..31)
    int j0 = (lane & 15) * 4;
    const float* wbase = &sW[half * 16 * 64 + j0];

    for (int n = warpId; n < NN; n += nWarps) {
        const float4* m4 = (const float4*)(motif + (size_t)n * 16);
        float m[16];
#pragma unroll
        for (int q = 0; q < 4; ++q) {
            float4 v = m4[q];     // uniform per warp -> broadcast
            m[4*q] = v.x; m[4*q+1] = v.y; m[4*q+2] = v.z; m[4*q+3] = v.w;
        }
        u64 a01 = 0ull, a23 = 0ull;
#pragma unroll
        for (int k = 0; k < 16; ++k) {
            float4 w = *(const float4*)&wbase[k * 64];
            u64 w01 = pk2(w.x, w.y), w23 = pk2(w.z, w.w);
            u64 mk = pk2(m[k], m[k]);
            a01 = ffma2(w01, mk, a01);
            a23 = ffma2(w23, mk, a23);
        }
        float4 o;
        upk2(a01, o.x, o.y); upk2(a23, o.z, o.w);
        __half2 h01 = __floats2half2_rn(o.x, o.y);
        __half2 h23 = __floats2half2_rn(o.z, o.w);
        uint2 st;
        st.x = *(unsigned*)&h01; st.y = *(unsigned*)&h23;
        __half* dst = (half ? g_tv16 : g_tu16) + (size_t)n * 64 + j0;
        *(uint2*)dst = st;     // 16 lanes -> contiguous 128B per half
    }
}

// ---------------- gate MLP: pipelined HFMA2 GEMM, 128 edges/tile ----------------
#define SFS 136   // sF row stride in halves
__global__ __launch_bounds__(256, 4) void k_edge_gate(const long long* __restrict__ ei,
                                                      const float* __restrict__ motif,
                                                      const float* __restrict__ w1,
                                                      const float* __restrict__ b1,
                                                      const float* __restrict__ w2,
                                                      const float* __restrict__ b2) {
    __shared__ __align__(16) __half sW16[32 * 64];       // W1 rows 32..63, [k][j] fp16
    __shared__ __align__(16) __half sF16[2][32 * SFS];   // feats [k][edge] fp16
    __shared__ int sS[2][128];
    __shared__ int sD[2][128];

    int tid = threadIdx.x;
    int tx = tid & 15;        // hidden group (j = tx*4 .. tx*4+3)
    int ty = tid >> 4;        // edge group  (edges ty*8 .. ty*8+7)

    for (int i = tid; i < 2048; i += 256) sW16[i] = __float2half(w1[2048 + i]);

    float b1r[4], w2r[4];
#pragma unroll
    for (int n = 0; n < 4; ++n) { b1r[n] = b1[tx * 4 + n]; w2r[n] = w2[tx * 4 + n]; }
    float b2s = b2[0];
    int is32 = g_is32;
    const int* e32 = (const int*)ei;

    int pr = tid >> 2;          // edge-pair slot 0..63 for gather phase
    int q  = tid & 3;           // quarter of the 16 motif dims

#define GATHER_PAIR(sFdst, s0_, d0_, s1_, d1_)                                          \
    {                                                                                   \
        float4 a0 = *(const float4*)(motif + (size_t)(s0_) * 16 + q * 4);               \
        float4 b0v = *(const float4*)(motif + (size_t)(d0_) * 16 + q * 4);              \
        float4 a1 = *(const float4*)(motif + (size_t)(s1_) * 16 + q * 4);               \
        float4 b1v = *(const float4*)(motif + (size_t)(d1_) * 16 + q * 4);              \
        int k0 = q * 4;                                                                 \
        float d0a[4] = { fabsf(a0.x-b0v.x), fabsf(a0.y-b0v.y), fabsf(a0.z-b0v.z), fabsf(a0.w-b0v.w) }; \
        float d1a[4] = { fabsf(a1.x-b1v.x), fabsf(a1.y-b1v.y), fabsf(a1.z-b1v.z), fabsf(a1.w-b1v.w) }; \
        float p0a[4] = { a0.x*b0v.x, a0.y*b0v.y, a0.z*b0v.z, a0.w*b0v.w };              \
        float p1a[4] = { a1.x*b1v.x, a1.y*b1v.y, a1.z*b1v.z, a1.w*b1v.w };              \
        _Pragma("unroll")                                                               \
        for (int j = 0; j < 4; ++j) {                                                   \
            __half2 dm2 = __floats2half2_rn(d0a[j], d1a[j]);                            \
            __half2 pm2 = __floats2half2_rn(p0a[j], p1a[j]);                            \
            *(__half2*)&(sFdst)[(k0 + j) * SFS + 2 * pr] = dm2;                         \
            *(__half2*)&(sFdst)[(16 + k0 + j) * SFS + 2 * pr] = pm2;                    \
        }                                                                               \
    }

    // ---- preamble gather: first tile into buffer 0 ----
    {
        int e0 = blockIdx.x * 128 + 2 * pr;
        int s0, d0, s1, d1;
        if (is32) { s0 = e32[e0]; d0 = e32[EE + e0]; s1 = e32[e0+1]; d1 = e32[EE + e0+1]; }
        else      { s0 = (int)ei[e0]; d0 = (int)ei[EE + e0]; s1 = (int)ei[e0+1]; d1 = (int)ei[EE + e0+1]; }
        if (q == 0) { sS[0][2*pr] = s0; sD[0][2*pr] = d0; sS[0][2*pr+1] = s1; sD[0][2*pr+1] = d1; }
        GATHER_PAIR(sF16[0], s0, d0, s1, d1);
    }

    int buf = 0;
    for (int tile = blockIdx.x; tile < NTILES_G; tile += gridDim.x) {
        __syncthreads();   // sF[buf]/sS[buf] complete; sF[buf^1] free for writes
        int eBase = tile * 128;
        int nt = tile + gridDim.x;
        bool hasNext = (nt < NTILES_G);

        // ---- prefetch next tile's indices ----
        int pS0 = 0, pD0 = 0, pS1 = 0, pD1 = 0;
        if (hasNext) {
            int e0 = nt * 128 + 2 * pr;
            if (is32) { pS0 = e32[e0]; pD0 = e32[EE + e0]; pS1 = e32[e0+1]; pD1 = e32[EE + e0+1]; }
            else      { pS0 = (int)ei[e0]; pD0 = (int)ei[EE + e0]; pS1 = (int)ei[e0+1]; pD1 = (int)ei[EE + e0+1]; }
            if (q == 0) { sS[buf^1][2*pr] = pS0; sD[buf^1][2*pr] = pD0; sS[buf^1][2*pr+1] = pS1; sD[buf^1][2*pr+1] = pD1; }
        }

        // ---- GEMM: HFMA2, pairs along edges. acch[pair 4][hidden 4] ----
        __half2 acch[4][4];
#pragma unroll
        for (int i = 0; i < 4; ++i)
#pragma unroll
            for (int n = 0; n < 4; ++n) acch[i][n] = __half2half2(__float2half(0.f));

        const __half* sFb = sF16[buf];
#pragma unroll 16
        for (int k = 0; k < 32; ++k) {
            uint4 afq = *(const uint4*)&sFb[k * SFS + ty * 8];      // 4 edge-pairs (broadcast)
            uint2 wfq = *(const uint2*)&sW16[k * 64 + tx * 4];      // 4 hidden halves
            __half2 ap[4] = { *(__half2*)&afq.x, *(__half2*)&afq.y,
                              *(__half2*)&afq.z, *(__half2*)&afq.w };
            __half2 w01 = *(__half2*)&wfq.x, w23 = *(__half2*)&wfq.y;
            __half2 bp[4] = { __low2half2(w01), __high2half2(w01),
                              __low2half2(w23), __high2half2(w23) };
#pragma unroll
            for (int i = 0; i < 4; ++i)
#pragma unroll
                for (int n = 0; n < 4; ++n) acch[i][n] = __hfma2(ap[i], bp[n], acch[i][n]);
        }

        float acc[8][4];
#pragma unroll
        for (int i = 0; i < 4; ++i)
#pragma unroll
            for (int n = 0; n < 4; ++n) {
                float2 f = __half22float2(acch[i][n]);
                acc[2*i][n] = f.x; acc[2*i+1][n] = f.y;
            }

        // ---- epilogue: + tu[s] + tv[d] (fp16) + b1, relu, dot w2, reduce ----
        float gp[8];
#pragma unroll
        for (int i = 0; i < 8; ++i) {
            int sl = sS[buf][ty * 8 + i];
            int dl = sD[buf][ty * 8 + i];
            uint2 tu2 = *(const uint2*)(g_tu16 + (size_t)sl * 64 + tx * 4);
            uint2 tv2 = *(const uint2*)(g_tv16 + (size_t)dl * 64 + tx * 4);
            float2 uA = __half22float2(*(__half2*)&tu2.x);
            float2 uB = __half22float2(*(__half2*)&tu2.y);
            float2 vA = __half22float2(*(__half2*)&tv2.x);
            float2 vB = __half22float2(*(__half2*)&tv2.y);
            float h0 = fmaxf(acc[i][0] + uA.x + vA.x + b1r[0], 0.f);
            float h1 = fmaxf(acc[i][1] + uA.y + vA.y + b1r[1], 0.f);
            float h2 = fmaxf(acc[i][2] + uB.x + vB.x + b1r[2], 0.f);
            float h3 = fmaxf(acc[i][3] + uB.y + vB.y + b1r[3], 0.f);
            gp[i] = h0 * w2r[0] + h1 * w2r[1] + h2 * w2r[2] + h3 * w2r[3];
        }
#pragma unroll
        for (int off = 8; off; off >>= 1)
#pragma unroll
            for (int i = 0; i < 8; ++i)
                gp[i] += __shfl_xor_sync(0xffffffffu, gp[i], off);

        if (tx == 0) {
#pragma unroll
            for (int i = 0; i < 8; ++i) {
                int slot = ty * 8 + i;
                int e = eBase + slot;
                int dl = sD[buf][slot];
                float gate = 1.f / (1.f + __expf(-(gp[i] + b2s)));
                g_gate[e] = gate;
                g_src[e] = sS[buf][slot];
                g_dst[e] = dl;
                atomicAdd(&g_deg[dl], gate);
                g_off[e] = atomicAdd(&g_cnt[dl], 1);   // capture bucket offset
            }
        }

        // ---- gather next tile's motif feats ----
        if (hasNext) {
            GATHER_PAIR(sF16[buf ^ 1], pS0, pD0, pS1, pD1);
        }
        buf ^= 1;
    }
#undef GATHER_PAIR
}

// ---------------- prefix scan of counts -> per-block inclusive scan (2 barriers) ----------------
__global__ __launch_bounds__(1024) void k_scan1() {
    __shared__ int warpSums[32];
    int t = threadIdx.x;
    int i = blockIdx.x * 1024 + t;
    int v = (i < NN) ? g_cnt[i] : 0;
    int lane = t & 31, wid = t >> 5;

    int s = v;
#pragma unroll
    for (int off = 1; off < 32; off <<= 1) {
        int x = __shfl_up_sync(0xffffffffu, s, off);
        if (lane >= off) s += x;
    }
    if (lane == 31) warpSums[wid] = s;
    __syncthreads();
    if (wid == 0) {
        int ws = warpSums[lane];
#pragma unroll
        for (int off = 1; off < 32; off <<= 1) {
            int x = __shfl_up_sync(0xffffffffu, ws, off);
            if (lane >= off) ws += x;
        }
        warpSums[lane] = ws;
    }
    __syncthreads();
    int addv = wid ? warpSums[wid - 1] : 0;
    int incl = s + addv;
    if (i < NN) g_tmp[i] = incl;
    if (t == 1023) g_bsum[blockIdx.x] = incl;
}

// scan of block sums per-block in smem + rowptr/dinv
__global__ __launch_bounds__(256) void k_scan3() {
    __shared__ int sh[128];
    int t = threadIdx.x;
    if (t < 128) sh[t] = (t < NB_SCAN) ? g_bsum[t] : 0;
    __syncthreads();
#pragma unroll
    for (int off = 1; off < 128; off <<= 1) {
        int x = (t < 128 && t >= off) ? sh[t - off] : 0;
        __syncthreads();
        if (t < 128) sh[t] += x;
        __syncthreads();
    }
    int i = blockIdx.x * 256 + t;
    if (i >= NN) return;
    int b = i >> 10;
    int off = b ? sh[b - 1] : 0;
    int excl = g_tmp[i] - g_cnt[i] + off;
    g_rowptr[i] = excl;
    g_dinv[i] = rsqrtf(g_deg[i]);
    if (i == 0) g_rowptr[NN] = EE;
}

// ---------------- fill CSR (no atomics: p = rowptr[d] + off[e]) ----------------
__global__ void k_fill() {
    int e = blockIdx.x * 256 + threadIdx.x;
    if (e >= EE) return;
    int s = g_src[e], d = g_dst[e];
    float nrm = g_dinv[s] * g_gate[e] * g_dinv[d];
    int p = g_rowptr[d] + g_off[e];
    g_csr[p] = ((u64)(unsigned)__float_as_int(nrm) << 32) | (unsigned)s;
}

// ---------------- SGEMM (f32x2): C[M,BN] = A[M,128] @ B[128,BN]; optional fp16 out ----------------
template <int BN, bool ADD_BIAS, bool OUT_HALF>
__global__ __launch_bounds__(256) void k_gemm2(const float* __restrict__ A,
                                               const float* __restrict__ B,
                                               const float* __restrict__ bias,
                                               void* __restrict__ Cv, int M) {
    constexpr int TN = BN / 16;   // 8 for 128, 4 for 64
    __shared__ __align__(16) float As[16][132];
    __shared__ __align__(16) float Bs[16][BN];

    int tid = threadIdx.x;
    int tx = tid & 15, ty = tid >> 4;
    int rowBase = blockIdx.x * 128;

    u64 accp[4][TN];
#pragma unroll
    for (int p = 0; p < 4; ++p)
#pragma unroll
        for (int n = 0; n < TN; ++n) accp[p][n] = 0ull;

    int ar = tid >> 1;
    int ak = (tid & 1) * 8;

    for (int k0 = 0; k0 < 128; k0 += 16) {
        float4 a0 = make_float4(0.f,0.f,0.f,0.f), a1 = a0;
        int grow = rowBase + ar;
        if (grow < M) {
            a0 = *(const float4*)(A + (size_t)grow * 128 + k0 + ak);
            a1 = *(const float4*)(A + (size_t)grow * 128 + k0 + ak + 4);
        }
        As[ak + 0][ar] = a0.x; As[ak + 1][ar] = a0.y;
        As[ak + 2][ar] = a0.z; As[ak + 3][ar] = a0.w;
        As[ak + 4][ar] = a1.x; As[ak + 5][ar] = a1.y;
        As[ak + 6][ar] = a1.z; As[ak + 7][ar] = a1.w;

        if (BN == 128) {
            int br = tid >> 5, bc = (tid & 31) * 4;
            *(float4*)&Bs[br][bc]     = *(const float4*)(B + (size_t)(k0 + br) * BN + bc);
            *(float4*)&Bs[br + 8][bc] = *(const float4*)(B + (size_t)(k0 + br + 8) * BN + bc);
        } else {
            int br = tid >> 4, bc = (tid & 15) * 4;
            *(float4*)&Bs[br][bc] = *(const float4*)(B + (size_t)(k0 + br) * BN + bc);
        }
        __syncthreads();

#pragma unroll
        for (int k = 0; k < 16; ++k) {
            const u64* av0 = (const u64*)&As[k][ty * 4];
            const u64* av1 = (const u64*)&As[k][ty * 4 + 64];
            u64 ap[4] = { av0[0], av0[1], av1[0], av1[1] };
            float4 bv0 = *(const float4*)&Bs[k][tx * 4];
            u64 bp[TN];
            bp[0] = pk2(bv0.x, bv0.x); bp[1] = pk2(bv0.y, bv0.y);
            bp[2] = pk2(bv0.z, bv0.z); bp[3] = pk2(bv0.w, bv0.w);
            if (TN == 8) {
                float4 bv1 = *(const float4*)&Bs[k][tx * 4 + 64];
                bp[4] = pk2(bv1.x, bv1.x); bp[5] = pk2(bv1.y, bv1.y);
                bp[6] = pk2(bv1.z, bv1.z); bp[7] = pk2(bv1.w, bv1.w);
            }
#pragma unroll
            for (int p = 0; p < 4; ++p)
#pragma unroll
                for (int n = 0; n < TN; ++n) accp[p][n] = ffma2(ap[p], bp[n], accp[p][n]);
        }
        __syncthreads();
    }

    float accf[8][TN];
#pragma unroll
    for (int p = 0; p < 4; ++p)
#pragma unroll
        for (int n = 0; n < TN; ++n) upk2(accp[p][n], accf[2*p][n], accf[2*p+1][n]);

#pragma unroll
    for (int m = 0; m < 8; ++m) {
        int r = rowBase + ty * 4 + ((m < 4) ? m : (64 + m - 4));
        if (r < M) {
            float4 v = make_float4(accf[m][0], accf[m][1], accf[m][2], accf[m][3]);
            if (ADD_BIAS) {
                v.x += bias[tx*4+0]; v.y += bias[tx*4+1];
                v.z += bias[tx*4+2]; v.w += bias[tx*4+3];
            }
            if (OUT_HALF) {
                __half* C = (__half*)Cv;
                __half2 p0 = __floats2half2_rn(v.x, v.y);
                __half2 p1 = __floats2half2_rn(v.z, v.w);
                uint2 st; st.x = *(unsigned*)&p0; st.y = *(unsigned*)&p1;
                *(uint2*)(C + (size_t)r * BN + tx * 4) = st;
                if (TN == 8) {
                    float4 v2 = make_float4(accf[m][4], accf[m][5], accf[m][6], accf[m][7]);
                    __half2 q0 = __floats2half2_rn(v2.x, v2.y);
                    __half2 q1 = __floats2half2_rn(v2.z, v2.w);
                    uint2 st2; st2.x = *(unsigned*)&q0; st2.y = *(unsigned*)&q1;
                    *(uint2*)(C + (size_t)r * BN + tx * 4 + 64) = st2;
                }
            } else {
                float* C = (float*)Cv;
                *(float4*)(C + (size_t)r * BN + tx * 4) = v;
                if (TN == 8) {
                    float4 v2 = make_float4(accf[m][4], accf[m][5], accf[m][6], accf[m][7]);
                    if (ADD_BIAS) {
                        v2.x += bias[tx*4+64]; v2.y += bias[tx*4+65];
                        v2.z += bias[tx*4+66]; v2.w += bias[tx*4+67];
                    }
                    *(float4*)(C + (size_t)r * BN + tx * 4 + 64) = v2;
                }
            }
        }
    }
}

// ---------------- fused aggregate (fp16 xw) + bias + LN + relu + residual ----------------
__global__ __launch_bounds__(256) void k_agg(const float* __restrict__ xin,
                                             float* __restrict__ xout,
                                             const float* __restrict__ cb,
                                             const float* __restrict__ lg,
                                             const float* __restrict__ lb) {
    int w = (blockIdx.x * 256 + threadIdx.x) >> 5;
    int lane = threadIdx.x & 31;
    if (w >= NN) return;

    int base = g_rowptr[w], end = g_rowptr[w + 1];
    float di = g_dinv[w];
    float sw = di * di;

    uint2 slf = *(const uint2*)(g_xw16 + (size_t)w * 128 + lane * 4);
    float2 sA = __half22float2(*(__half2*)&slf.x);
    float2 sB = __half22float2(*(__half2*)&slf.y);
    float4 acc = make_float4(sA.x * sw, sA.y * sw, sB.x * sw, sB.y * sw);

    int i = base;
    for (; i + 4 <= end; i += 4) {
        u64 c0 = g_csr[i],   c1 = g_csr[i+1];
        u64 c2 = g_csr[i+2], c3 = g_csr[i+3];
        int   s0 = (int)(unsigned)c0, s1 = (int)(unsigned)c1;
        int   s2 = (int)(unsigned)c2, s3 = (int)(unsigned)c3;
        float n0 = __int_as_float((int)(c0 >> 32));
        float n1 = __int_as_float((int)(c1 >> 32));
        float n2 = __int_as_float((int)(c2 >> 32));
        float n3 = __int_as_float((int)(c3 >> 32));
        uint2 h0 = *(const uint2*)(g_xw16 + (size_t)s0 * 128 + lane * 4);
        uint2 h1 = *(const uint2*)(g_xw16 + (size_t)s1 * 128 + lane * 4);
        uint2 h2 = *(const uint2*)(g_xw16 + (size_t)s2 * 128 + lane * 4);
        uint2 h3 = *(const uint2*)(g_xw16 + (size_t)s3 * 128 + lane * 4);
        float2 a0 = __half22float2(*(__half2*)&h0.x), b0 = __half22float2(*(__half2*)&h0.y);
        float2 a1 = __half22float2(*(__half2*)&h1.x), b1 = __half22float2(*(__half2*)&h1.y);
        float2 a2 = __half22float2(*(__half2*)&h2.x), b2 = __half22float2(*(__half2*)&h2.y);
        float2 a3 = __half22float2(*(__half2*)&h3.x), b3 = __half22float2(*(__half2*)&h3.y);
        acc.x += n0 * a0.x + n1 * a1.x + n2 * a2.x + n3 * a3.x;
        acc.y += n0 * a0.y + n1 * a1.y + n2 * a2.y + n3 * a3.y;
        acc.z += n0 * b0.x + n1 * b1.x + n2 * b2.x + n3 * b3.x;
        acc.w += n0 * b0.y + n1 * b1.y + n2 * b2.y + n3 * b3.y;
    }
    for (; i < end; ++i) {
        u64 c0 = g_csr[i];
        int s0 = (int)(unsigned)c0;
        float n0 = __int_as_float((int)(c0 >> 32));
        uint2 h0 = *(const uint2*)(g_xw16 + (size_t)s0 * 128 + lane * 4);
        float2 a0 = __half22float2(*(__half2*)&h0.x), b0 = __half22float2(*(__half2*)&h0.y);
        acc.x += n0 * a0.x; acc.y += n0 * a0.y;
        acc.z += n0 * b0.x; acc.w += n0 * b0.y;
    }

    float4 b = *(const float4*)(cb + lane * 4);
    acc.x += b.x; acc.y += b.y; acc.z += b.z; acc.w += b.w;

    float ssum = acc.x + acc.y + acc.z + acc.w;
#pragma unroll
    for (int o = 16; o; o >>= 1) ssum += __shfl_xor_sync(0xffffffffu, ssum, o);
    float mean = ssum * 0.0078125f;
    float d0 = acc.x - mean, d1 = acc.y - mean, d2 = acc.z - mean, d3 = acc.w - mean;
    float ss = d0*d0 + d1*d1 + d2*d2 + d3*d3;
#pragma unroll
    for (int o = 16; o; o >>= 1) ss += __shfl_xor_sync(0xffffffffu, ss, o);
    float inv = rsqrtf(ss * 0.0078125f + 1e-5f);

    float4 g = *(const float4*)(lg + lane * 4);
    float4 bb = *(const float4*)(lb + lane * 4);
    float4 xi = *(const float4*)(xin + (size_t)w * 128 + lane * 4);
    float4 o4;
    o4.x = xi.x + fmaxf(d0 * inv * g.x + bb.x, 0.f);
    o4.y = xi.y + fmaxf(d1 * inv * g.y + bb.y, 0.f);
    o4.z = xi.z + fmaxf(d2 * inv * g.z + bb.z, 0.f);
    o4.w = xi.w + fmaxf(d3 * inv * g.w + bb.w, 0.f);
    *(float4*)(xout + (size_t)w * 128 + lane * 4) = o4;
}

// ---------------- orchestration ----------------
extern "C" void kernel_launch(void* const* d_in, const int* in_sizes, int n_in,
                              void* d_out, int out_size) {
    const float*     x     = (const float*)d_in[0];
    const float*     motif = (const float*)d_in[1];
    const long long* ei    = (const long long*)d_in[2];
    const float*     gw1   = (const float*)d_in[3];
    const float*     gb1   = (const float*)d_in[4];
    const float*     gw2   = (const float*)d_in[5];
    const float*     gb2   = (const float*)d_in[6];
    const float*     cw    = (const float*)d_in[7];
    const float*     cb    = (const float*)d_in[8];
    const float*     lg    = (const float*)d_in[9];
    const float*     lb    = (const float*)d_in[10];
    const float*     hw    = (const float*)d_in[11];
    const float*     hb    = (const float*)d_in[12];
    float* out = (float*)d_out;

    float* x1p; void* xwp;
    cudaGetSymbolAddress((void**)&x1p, g_x1);
    cudaGetSymbolAddress(&xwp, g_xw16);

    // side stream + events, created once
    static cudaStream_t s2 = nullptr;
    static cudaEvent_t evF = nullptr, evJ = nullptr;
    if (s2 == nullptr) {
        cudaStreamCreateWithFlags(&s2, cudaStreamNonBlocking);
        cudaEventCreateWithFlags(&evF, cudaEventDisableTiming);
        cudaEventCreateWithFlags(&evJ, cudaEventDisableTiming);
    }

    // fork: layer-1 conv GEMM is independent of the gate/CSR chain
    cudaEventRecord(evF, 0);
    cudaStreamWaitEvent(s2, evF, 0);
    k_gemm2<128, false, true><<<(NN + 127) / 128, 256, 0, s2>>>(x, cw, nullptr, xwp, NN);
    cudaEventRecord(evJ, s2);

    // main chain: init -> node_pre -> gate -> scan -> fill
    k_init<<<(NN + 255) / 256, 256>>>(ei);
    k_node_pre<<<592, 256>>>(motif, gw1);
    k_edge_gate<<<1184, 256>>>(ei, motif, gw1, gb1, gw2, gb2);
    k_scan1<<<NB_SCAN, 1024>>>();
    k_scan3<<<(NN + 255) / 256, 256>>>();
    k_fill<<<EE / 256, 256>>>();

    // join: agg layer 1 needs xw from side stream
    cudaStreamWaitEvent(0, evJ, 0);
    k_agg<<<(NN + 7) / 8, 256>>>(x, x1p, cb, lg, lb);

    // layer 2 (serial: depends on x1)
    k_gemm2<128, false, true><<<(NN + 127) / 128, 256>>>(x1p, cw + 128 * 128, nullptr, xwp, NN);
    k_agg<<<(NN + 7) / 8, 256>>>(x1p, x1p, cb + 128, lg + 128, lb + 128);

    k_gemm2<64, true, false><<<(NN + 127) / 128, 256>>>(x1p, hw, hb, out, NN);
}

// round 15
// speedup vs baseline: 1.0893x; 1.0893x over previous
#include <cuda_runtime.h>
#include <cuda_fp16.h>
#include <math.h>

#define NN 100000
#define EE 1600000
#define NB_SCAN 98        // ceil(NN/1024)
#define NTILES_G (EE / 128)

typedef unsigned long long u64;

// ---------------- packed f32x2 helpers (Blackwell) ----------------
__device__ __forceinline__ u64 pk2(float lo, float hi) {
    u64 r; asm("mov.b64 %0, {%1, %2};" : "=l"(r) : "f"(lo), "f"(hi)); return r;
}
__device__ __forceinline__ void upk2(u64 v, float& lo, float& hi) {
    asm("mov.b64 {%0, %1}, %2;" : "=f"(lo), "=f"(hi) : "l"(v));
}
__device__ __forceinline__ u64 ffma2(u64 a, u64 b, u64 c) {
    u64 d; asm("fma.rn.f32x2 %0, %1, %2, %3;" : "=l"(d) : "l"(a), "l"(b), "l"(c)); return d;
}

// ---------------- scratch (static device globals; no allocs) ----------------
__device__ __align__(16) float  g_gate[EE];
__device__ __align__(16) int    g_src[EE];
__device__ __align__(16) int    g_dst[EE];
__device__ __align__(16) int    g_off[EE];          // within-bucket offset (from gate atomics)
__device__ __align__(16) u64    g_csr[EE];          // hi: norm bits, lo: src
__device__ __align__(16) float  g_deg[NN];
__device__ __align__(16) float  g_dinv[NN];
__device__ __align__(16) int    g_cnt[NN];
__device__ __align__(16) int    g_tmp[NN];
__device__ __align__(16) int    g_rowptr[NN + 1];
__device__ __align__(16) int    g_bsum[NB_SCAN];
__device__ __align__(16) __half g_tu16[NN * 64];
__device__ __align__(16) __half g_tv16[NN * 64];
__device__ __align__(16) __half g_xw16[NN * 128];
__device__ __align__(16) float  g_x1[NN * 128];
__device__ int g_is32;

// ---------------- init (deg=1 self-loop, cnt=0) + dtype detect ----------------
__global__ void k_init(const long long* __restrict__ ei) {
    int i = blockIdx.x * 256 + threadIdx.x;
    if (i < NN) { g_deg[i] = 1.0f; g_cnt[i] = 0; }
    if (i == 0) {
        int bad = 0;
        for (int t = 0; t < 128; ++t) {
            long long v = ei[t];
            if (v < 0 || v >= (long long)NN) { bad = 1; break; }
        }
        g_is32 = bad;
    }
}

// ---------------- node_pre: warp per node, fp16 output, coalesced stores ----------------
__global__ __launch_bounds__(256) void k_node_pre(const float* __restrict__ motif,
                                                  const float* __restrict__ w1) {
    __shared__ __align__(16) float sW[32 * 64];
    for (int i = threadIdx.x; i < 2048; i += 256) sW[i] = w1[i];
    __syncthreads();

    int lane = threadIdx.x & 31;
    int warpId = (blockIdx.x * 256 + threadIdx.x) >> 5;
    int nWarps = (gridDim.x * 256) >> 5;
    int half = lane >> 4;              // 0: tu (W rows 0..15), 1: tv (rows 16..31)
    int j0 = (lane & 15) * 4;
    const float* wbase = &sW[half * 16 * 64 + j0];

    for (int n = warpId; n < NN; n += nWarps) {
        const float4* m4 = (const float4*)(motif + (size_t)n * 16);
        float m[16];
#pragma unroll
        for (int q = 0; q < 4; ++q) {
            float4 v = m4[q];     // uniform per warp -> broadcast
            m[4*q] = v.x; m[4*q+1] = v.y; m[4*q+2] = v.z; m[4*q+3] = v.w;
        }
        u64 a01 = 0ull, a23 = 0ull;
#pragma unroll
        for (int k = 0; k < 16; ++k) {
            float4 w = *(const float4*)&wbase[k * 64];
            u64 w01 = pk2(w.x, w.y), w23 = pk2(w.z, w.w);
            u64 mk = pk2(m[k], m[k]);
            a01 = ffma2(w01, mk, a01);
            a23 = ffma2(w23, mk, a23);
        }
        float4 o;
        upk2(a01, o.x, o.y); upk2(a23, o.z, o.w);
        __half2 h01 = __floats2half2_rn(o.x, o.y);
        __half2 h23 = __floats2half2_rn(o.z, o.w);
        uint2 st;
        st.x = *(unsigned*)&h01; st.y = *(unsigned*)&h23;
        __half* dst = (half ? g_tv16 : g_tu16) + (size_t)n * 64 + j0;
        *(uint2*)dst = st;     // 16 lanes -> contiguous 128B per half
    }
}

// ---------------- gate MLP: pipelined HFMA2 GEMM, 128 edges/tile ----------------
#define SFS 136   // sF row stride in halves
__global__ __launch_bounds__(256, 4) void k_edge_gate(const long long* __restrict__ ei,
                                                      const float* __restrict__ motif,
                                                      const float* __restrict__ w1,
                                                      const float* __restrict__ b1,
                                                      const float* __restrict__ w2,
                                                      const float* __restrict__ b2) {
    __shared__ __align__(16) __half sW16[32 * 64];       // W1 rows 32..63, [k][j] fp16
    __shared__ __align__(16) __half sF16[2][32 * SFS];   // feats [k][edge] fp16
    __shared__ int sS[2][128];
    __shared__ int sD[2][128];

    int tid = threadIdx.x;
    int tx = tid & 15;        // hidden group (j = tx*4 .. tx*4+3)
    int ty = tid >> 4;        // edge group  (edges ty*8 .. ty*8+7)

    for (int i = tid; i < 2048; i += 256) sW16[i] = __float2half(w1[2048 + i]);

    float b1r[4], w2r[4];
#pragma unroll
    for (int n = 0; n < 4; ++n) { b1r[n] = b1[tx * 4 + n]; w2r[n] = w2[tx * 4 + n]; }
    float b2s = b2[0];
    int is32 = g_is32;
    const int* e32 = (const int*)ei;

    int pr = tid >> 2;          // edge-pair slot 0..63 for gather phase
    int q  = tid & 3;           // quarter of the 16 motif dims

#define GATHER_PAIR(sFdst, s0_, d0_, s1_, d1_)                                          \
    {                                                                                   \
        float4 a0 = *(const float4*)(motif + (size_t)(s0_) * 16 + q * 4);               \
        float4 b0v = *(const float4*)(motif + (size_t)(d0_) * 16 + q * 4);              \
        float4 a1 = *(const float4*)(motif + (size_t)(s1_) * 16 + q * 4);               \
        float4 b1v = *(const float4*)(motif + (size_t)(d1_) * 16 + q * 4);              \
        int k0 = q * 4;                                                                 \
        float d0a[4] = { fabsf(a0.x-b0v.x), fabsf(a0.y-b0v.y), fabsf(a0.z-b0v.z), fabsf(a0.w-b0v.w) }; \
        float d1a[4] = { fabsf(a1.x-b1v.x), fabsf(a1.y-b1v.y), fabsf(a1.z-b1v.z), fabsf(a1.w-b1v.w) }; \
        float p0a[4] = { a0.x*b0v.x, a0.y*b0v.y, a0.z*b0v.z, a0.w*b0v.w };              \
        float p1a[4] = { a1.x*b1v.x, a1.y*b1v.y, a1.z*b1v.z, a1.w*b1v.w };              \
        _Pragma("unroll")                                                               \
        for (int j = 0; j < 4; ++j) {                                                   \
            __half2 dm2 = __floats2half2_rn(d0a[j], d1a[j]);                            \
            __half2 pm2 = __floats2half2_rn(p0a[j], p1a[j]);                            \
            *(__half2*)&(sFdst)[(k0 + j) * SFS + 2 * pr] = dm2;                         \
            *(__half2*)&(sFdst)[(16 + k0 + j) * SFS + 2 * pr] = pm2;                    \
        }                                                                               \
    }

    // ---- preamble gather: first tile into buffer 0 ----
    {
        int e0 = blockIdx.x * 128 + 2 * pr;
        int s0, d0, s1, d1;
        if (is32) { s0 = e32[e0]; d0 = e32[EE + e0]; s1 = e32[e0+1]; d1 = e32[EE + e0+1]; }
        else      { s0 = (int)ei[e0]; d0 = (int)ei[EE + e0]; s1 = (int)ei[e0+1]; d1 = (int)ei[EE + e0+1]; }
        if (q == 0) { sS[0][2*pr] = s0; sD[0][2*pr] = d0; sS[0][2*pr+1] = s1; sD[0][2*pr+1] = d1; }
        GATHER_PAIR(sF16[0], s0, d0, s1, d1);
    }

    int buf = 0;
    for (int tile = blockIdx.x; tile < NTILES_G; tile += gridDim.x) {
        __syncthreads();   // sF[buf]/sS[buf] complete; sF[buf^1] free for writes
        int eBase = tile * 128;
        int nt = tile + gridDim.x;
        bool hasNext = (nt < NTILES_G);

        // ---- prefetch next tile's indices ----
        int pS0 = 0, pD0 = 0, pS1 = 0, pD1 = 0;
        if (hasNext) {
            int e0 = nt * 128 + 2 * pr;
            if (is32) { pS0 = e32[e0]; pD0 = e32[EE + e0]; pS1 = e32[e0+1]; pD1 = e32[EE + e0+1]; }
            else      { pS0 = (int)ei[e0]; pD0 = (int)ei[EE + e0]; pS1 = (int)ei[e0+1]; pD1 = (int)ei[EE + e0+1]; }
            if (q == 0) { sS[buf^1][2*pr] = pS0; sD[buf^1][2*pr] = pD0; sS[buf^1][2*pr+1] = pS1; sD[buf^1][2*pr+1] = pD1; }
        }

        // ---- GEMM: HFMA2, pairs along edges. acch[pair 4][hidden 4] ----
        __half2 acch[4][4];
#pragma unroll
        for (int i = 0; i < 4; ++i)
#pragma unroll
            for (int n = 0; n < 4; ++n) acch[i][n] = __half2half2(__float2half(0.f));

        const __half* sFb = sF16[buf];
#pragma unroll 16
        for (int k = 0; k < 32; ++k) {
            uint4 afq = *(const uint4*)&sFb[k * SFS + ty * 8];      // 4 edge-pairs (broadcast)
            uint2 wfq = *(const uint2*)&sW16[k * 64 + tx * 4];      // 4 hidden halves
            __half2 ap[4] = { *(__half2*)&afq.x, *(__half2*)&afq.y,
                              *(__half2*)&afq.z, *(__half2*)&afq.w };
            __half2 w01 = *(__half2*)&wfq.x, w23 = *(__half2*)&wfq.y;
            __half2 bp[4] = { __low2half2(w01), __high2half2(w01),
                              __low2half2(w23), __high2half2(w23) };
#pragma unroll
            for (int i = 0; i < 4; ++i)
#pragma unroll
                for (int n = 0; n < 4; ++n) acch[i][n] = __hfma2(ap[i], bp[n], acch[i][n]);
        }

        float acc[8][4];
#pragma unroll
        for (int i = 0; i < 4; ++i)
#pragma unroll
            for (int n = 0; n < 4; ++n) {
                float2 f = __half22float2(acch[i][n]);
                acc[2*i][n] = f.x; acc[2*i+1][n] = f.y;
            }

        // ---- epilogue: + tu[s] + tv[d] (fp16) + b1, relu, dot w2, reduce ----
        float gp[8];
#pragma unroll
        for (int i = 0; i < 8; ++i) {
            int sl = sS[buf][ty * 8 + i];
            int dl = sD[buf][ty * 8 + i];
            uint2 tu2 = *(const uint2*)(g_tu16 + (size_t)sl * 64 + tx * 4);
            uint2 tv2 = *(const uint2*)(g_tv16 + (size_t)dl * 64 + tx * 4);
            float2 uA = __half22float2(*(__half2*)&tu2.x);
            float2 uB = __half22float2(*(__half2*)&tu2.y);
            float2 vA = __half22float2(*(__half2*)&tv2.x);
            float2 vB = __half22float2(*(__half2*)&tv2.y);
            float h0 = fmaxf(acc[i][0] + uA.x + vA.x + b1r[0], 0.f);
            float h1 = fmaxf(acc[i][1] + uA.y + vA.y + b1r[1], 0.f);
            float h2 = fmaxf(acc[i][2] + uB.x + vB.x + b1r[2], 0.f);
            float h3 = fmaxf(acc[i][3] + uB.y + vB.y + b1r[3], 0.f);
            gp[i] = h0 * w2r[0] + h1 * w2r[1] + h2 * w2r[2] + h3 * w2r[3];
        }
#pragma unroll
        for (int off = 8; off; off >>= 1)
#pragma unroll
            for (int i = 0; i < 8; ++i)
                gp[i] += __shfl_xor_sync(0xffffffffu, gp[i], off);

        // ---- distributed writeback: lane tx<8 owns edge tx of its half ----
        float myGp = gp[0];
#pragma unroll
        for (int i = 1; i < 8; ++i) if (tx == i) myGp = gp[i];   // predicated selects

        if (tx < 8) {
            int slot = ty * 8 + tx;
            int e = eBase + slot;
            int dl = sD[buf][slot];
            float gate = 1.f / (1.f + __expf(-(myGp + b2s)));
            g_gate[e] = gate;
            g_src[e] = sS[buf][slot];
            g_dst[e] = dl;
            atomicAdd(&g_deg[dl], gate);                 // RED, no return
            g_off[e] = atomicAdd(&g_cnt[dl], 1);         // 1 returning atomic per lane, parallel
        }

        // ---- gather next tile's motif feats ----
        if (hasNext) {
            GATHER_PAIR(sF16[buf ^ 1], pS0, pD0, pS1, pD1);
        }
        buf ^= 1;
    }
#undef GATHER_PAIR
}

// ---------------- prefix scan of counts -> per-block inclusive scan (2 barriers) ----------------
__global__ __launch_bounds__(1024) void k_scan1() {
    __shared__ int warpSums[32];
    int t = threadIdx.x;
    int i = blockIdx.x * 1024 + t;
    int v = (i < NN) ? g_cnt[i] : 0;
    int lane = t & 31, wid = t >> 5;

    int s = v;
#pragma unroll
    for (int off = 1; off < 32; off <<= 1) {
        int x = __shfl_up_sync(0xffffffffu, s, off);
        if (lane >= off) s += x;
    }
    if (lane == 31) warpSums[wid] = s;
    __syncthreads();
    if (wid == 0) {
        int ws = warpSums[lane];
#pragma unroll
        for (int off = 1; off < 32; off <<= 1) {
            int x = __shfl_up_sync(0xffffffffu, ws, off);
            if (lane >= off) ws += x;
        }
        warpSums[lane] = ws;
    }
    __syncthreads();
    int addv = wid ? warpSums[wid - 1] : 0;
    int incl = s + addv;
    if (i < NN) g_tmp[i] = incl;
    if (t == 1023) g_bsum[blockIdx.x] = incl;
}

// scan of block sums per-block in smem + rowptr/dinv
__global__ __launch_bounds__(256) void k_scan3() {
    __shared__ int sh[128];
    int t = threadIdx.x;
    if (t < 128) sh[t] = (t < NB_SCAN) ? g_bsum[t] : 0;
    __syncthreads();
#pragma unroll
    for (int off = 1; off < 128; off <<= 1) {
        int x = (t < 128 && t >= off) ? sh[t - off] : 0;
        __syncthreads();
        if (t < 128) sh[t] += x;
        __syncthreads();
    }
    int i = blockIdx.x * 256 + t;
    if (i >= NN) return;
    int b = i >> 10;
    int off = b ? sh[b - 1] : 0;
    int excl = g_tmp[i] - g_cnt[i] + off;
    g_rowptr[i] = excl;
    g_dinv[i] = rsqrtf(g_deg[i]);
    if (i == 0) g_rowptr[NN] = EE;
}

// ---------------- fill CSR (no atomics: p = rowptr[d] + off[e]) ----------------
__global__ void k_fill() {
    int e = blockIdx.x * 256 + threadIdx.x;
    if (e >= EE) return;
    int s = g_src[e], d = g_dst[e];
    float nrm = g_dinv[s] * g_gate[e] * g_dinv[d];
    int p = g_rowptr[d] + g_off[e];
    g_csr[p] = ((u64)(unsigned)__float_as_int(nrm) << 32) | (unsigned)s;
}

// ---------------- SGEMM (f32x2): C[M,BN] = A[M,128] @ B[128,BN]; optional fp16 out ----------------
template <int BN, bool ADD_BIAS, bool OUT_HALF>
__global__ __launch_bounds__(256) void k_gemm2(const float* __restrict__ A,
                                               const float* __restrict__ B,
                                               const float* __restrict__ bias,
                                               void* __restrict__ Cv, int M) {
    constexpr int TN = BN / 16;   // 8 for 128, 4 for 64
    __shared__ __align__(16) float As[16][132];
    __shared__ __align__(16) float Bs[16][BN];

    int tid = threadIdx.x;
    int tx = tid & 15, ty = tid >> 4;
    int rowBase = blockIdx.x * 128;

    u64 accp[4][TN];
#pragma unroll
    for (int p = 0; p < 4; ++p)
#pragma unroll
        for (int n = 0; n < TN; ++n) accp[p][n] = 0ull;

    int ar = tid >> 1;
    int ak = (tid & 1) * 8;

    for (int k0 = 0; k0 < 128; k0 += 16) {
        float4 a0 = make_float4(0.f,0.f,0.f,0.f), a1 = a0;
        int grow = rowBase + ar;
        if (grow < M) {
            a0 = *(const float4*)(A + (size_t)grow * 128 + k0 + ak);
            a1 = *(const float4*)(A + (size_t)grow * 128 + k0 + ak + 4);
        }
        As[ak + 0][ar] = a0.x; As[ak + 1][ar] = a0.y;
        As[ak + 2][ar] = a0.z; As[ak + 3][ar] = a0.w;
        As[ak + 4][ar] = a1.x; As[ak + 5][ar] = a1.y;
        As[ak + 6][ar] = a1.z; As[ak + 7][ar] = a1.w;

        if (BN == 128) {
            int br = tid >> 5, bc = (tid & 31) * 4;
            *(float4*)&Bs[br][bc]     = *(const float4*)(B + (size_t)(k0 + br) * BN + bc);
            *(float4*)&Bs[br + 8][bc] = *(const float4*)(B + (size_t)(k0 + br + 8) * BN + bc);
        } else {
            int br = tid >> 4, bc = (tid & 15) * 4;
            *(float4*)&Bs[br][bc] = *(const float4*)(B + (size_t)(k0 + br) * BN + bc);
        }
        __syncthreads();

#pragma unroll
        for (int k = 0; k < 16; ++k) {
            const u64* av0 = (const u64*)&As[k][ty * 4];
            const u64* av1 = (const u64*)&As[k][ty * 4 + 64];
            u64 ap[4] = { av0[0], av0[1], av1[0], av1[1] };
            float4 bv0 = *(const float4*)&Bs[k][tx * 4];
            u64 bp[TN];
            bp[0] = pk2(bv0.x, bv0.x); bp[1] = pk2(bv0.y, bv0.y);
            bp[2] = pk2(bv0.z, bv0.z); bp[3] = pk2(bv0.w, bv0.w);
            if (TN == 8) {
                float4 bv1 = *(const float4*)&Bs[k][tx * 4 + 64];
                bp[4] = pk2(bv1.x, bv1.x); bp[5] = pk2(bv1.y, bv1.y);
                bp[6] = pk2(bv1.z, bv1.z); bp[7] = pk2(bv1.w, bv1.w);
            }
#pragma unroll
            for (int p = 0; p < 4; ++p)
#pragma unroll
                for (int n = 0; n < TN; ++n) accp[p][n] = ffma2(ap[p], bp[n], accp[p][n]);
        }
        __syncthreads();
    }

    float accf[8][TN];
#pragma unroll
    for (int p = 0; p < 4; ++p)
#pragma unroll
        for (int n = 0; n < TN; ++n) upk2(accp[p][n], accf[2*p][n], accf[2*p+1][n]);

#pragma unroll
    for (int m = 0; m < 8; ++m) {
        int r = rowBase + ty * 4 + ((m < 4) ? m : (64 + m - 4));
        if (r < M) {
            float4 v = make_float4(accf[m][0], accf[m][1], accf[m][2], accf[m][3]);
            if (ADD_BIAS) {
                v.x += bias[tx*4+0]; v.y += bias[tx*4+1];
                v.z += bias[tx*4+2]; v.w += bias[tx*4+3];
            }
            if (OUT_HALF) {
                __half* C = (__half*)Cv;
                __half2 p0 = __floats2half2_rn(v.x, v.y);
                __half2 p1 = __floats2half2_rn(v.z, v.w);
                uint2 st; st.x = *(unsigned*)&p0; st.y = *(unsigned*)&p1;
                *(uint2*)(C + (size_t)r * BN + tx * 4) = st;
                if (TN == 8) {
                    float4 v2 = make_float4(accf[m][4], accf[m][5], accf[m][6], accf[m][7]);
                    __half2 q0 = __floats2half2_rn(v2.x, v2.y);
                    __half2 q1 = __floats2half2_rn(v2.z, v2.w);
                    uint2 st2; st2.x = *(unsigned*)&q0; st2.y = *(unsigned*)&q1;
                    *(uint2*)(C + (size_t)r * BN + tx * 4 + 64) = st2;
                }
            } else {
                float* C = (float*)Cv;
                *(float4*)(C + (size_t)r * BN + tx * 4) = v;
                if (TN == 8) {
                    float4 v2 = make_float4(accf[m][4], accf[m][5], accf[m][6], accf[m][7]);
                    if (ADD_BIAS) {
                        v2.x += bias[tx*4+64]; v2.y += bias[tx*4+65];
                        v2.z += bias[tx*4+66]; v2.w += bias[tx*4+67];
                    }
                    *(float4*)(C + (size_t)r * BN + tx * 4 + 64) = v2;
                }
            }
        }
    }
}

// ---------------- fused aggregate (fp16 xw) + bias + LN + relu + residual ----------------
__global__ __launch_bounds__(256) void k_agg(const float* __restrict__ xin,
                                             float* __restrict__ xout,
                                             const float* __restrict__ cb,
                                             const float* __restrict__ lg,
                                             const float* __restrict__ lb) {
    int w = (blockIdx.x * 256 + threadIdx.x) >> 5;
    int lane = threadIdx.x & 31;
    if (w >= NN) return;

    int base = g_rowptr[w], end = g_rowptr[w + 1];
    float di = g_dinv[w];
    float sw = di * di;

    uint2 slf = *(const uint2*)(g_xw16 + (size_t)w * 128 + lane * 4);
    float2 sA = __half22float2(*(__half2*)&slf.x);
    float2 sB = __half22float2(*(__half2*)&slf.y);
    float4 acc = make_float4(sA.x * sw, sA.y * sw, sB.x * sw, sB.y * sw);

    int i = base;
    for (; i + 4 <= end; i += 4) {
        u64 c0 = g_csr[i],   c1 = g_csr[i+1];
        u64 c2 = g_csr[i+2], c3 = g_csr[i+3];
        int   s0 = (int)(unsigned)c0, s1 = (int)(unsigned)c1;
        int   s2 = (int)(unsigned)c2, s3 = (int)(unsigned)c3;
        float n0 = __int_as_float((int)(c0 >> 32));
        float n1 = __int_as_float((int)(c1 >> 32));
        float n2 = __int_as_float((int)(c2 >> 32));
        float n3 = __int_as_float((int)(c3 >> 32));
        uint2 h0 = *(const uint2*)(g_xw16 + (size_t)s0 * 128 + lane * 4);
        uint2 h1 = *(const uint2*)(g_xw16 + (size_t)s1 * 128 + lane * 4);
        uint2 h2 = *(const uint2*)(g_xw16 + (size_t)s2 * 128 + lane * 4);
        uint2 h3 = *(const uint2*)(g_xw16 + (size_t)s3 * 128 + lane * 4);
        float2 a0 = __half22float2(*(__half2*)&h0.x), b0 = __half22float2(*(__half2*)&h0.y);
        float2 a1 = __half22float2(*(__half2*)&h1.x), b1 = __half22float2(*(__half2*)&h1.y);
        float2 a2 = __half22float2(*(__half2*)&h2.x), b2 = __half22float2(*(__half2*)&h2.y);
        float2 a3 = __half22float2(*(__half2*)&h3.x), b3 = __half22float2(*(__half2*)&h3.y);
        acc.x += n0 * a0.x + n1 * a1.x + n2 * a2.x + n3 * a3.x;
        acc.y += n0 * a0.y + n1 * a1.y + n2 * a2.y + n3 * a3.y;
        acc.z += n0 * b0.x + n1 * b1.x + n2 * b2.x + n3 * b3.x;
        acc.w += n0 * b0.y + n1 * b1.y + n2 * b2.y + n3 * b3.y;
    }
    for (; i < end; ++i) {
        u64 c0 = g_csr[i];
        int s0 = (int)(unsigned)c0;
        float n0 = __int_as_float((int)(c0 >> 32));
        uint2 h0 = *(const uint2*)(g_xw16 + (size_t)s0 * 128 + lane * 4);
        float2 a0 = __half22float2(*(__half2*)&h0.x), b0 = __half22float2(*(__half2*)&h0.y);
        acc.x += n0 * a0.x; acc.y += n0 * a0.y;
        acc.z += n0 * b0.x; acc.w += n0 * b0.y;
    }

    float4 b = *(const float4*)(cb + lane * 4);
    acc.x += b.x; acc.y += b.y; acc.z += b.z; acc.w += b.w;

    float ssum = acc.x + acc.y + acc.z + acc.w;
#pragma unroll
    for (int o = 16; o; o >>= 1) ssum += __shfl_xor_sync(0xffffffffu, ssum, o);
    float mean = ssum * 0.0078125f;
    float d0 = acc.x - mean, d1 = acc.y - mean, d2 = acc.z - mean, d3 = acc.w - mean;
    float ss = d0*d0 + d1*d1 + d2*d2 + d3*d3;
#pragma unroll
    for (int o = 16; o; o >>= 1) ss += __shfl_xor_sync(0xffffffffu, ss, o);
    float inv = rsqrtf(ss * 0.0078125f + 1e-5f);

    float4 g = *(const float4*)(lg + lane * 4);
    float4 bb = *(const float4*)(lb + lane * 4);
    float4 xi = *(const float4*)(xin + (size_t)w * 128 + lane * 4);
    float4 o4;
    o4.x = xi.x + fmaxf(d0 * inv * g.x + bb.x, 0.f);
    o4.y = xi.y + fmaxf(d1 * inv * g.y + bb.y, 0.f);
    o4.z = xi.z + fmaxf(d2 * inv * g.z + bb.z, 0.f);
    o4.w = xi.w + fmaxf(d3 * inv * g.w + bb.w, 0.f);
    *(float4*)(xout + (size_t)w * 128 + lane * 4) = o4;
}

// ---------------- orchestration ----------------
extern "C" void kernel_launch(void* const* d_in, const int* in_sizes, int n_in,
                              void* d_out, int out_size) {
    const float*     x     = (const float*)d_in[0];
    const float*     motif = (const float*)d_in[1];
    const long long* ei    = (const long long*)d_in[2];
    const float*     gw1   = (const float*)d_in[3];
    const float*     gb1   = (const float*)d_in[4];
    const float*     gw2   = (const float*)d_in[5];
    const float*     gb2   = (const float*)d_in[6];
    const float*     cw    = (const float*)d_in[7];
    const float*     cb    = (const float*)d_in[8];
    const float*     lg    = (const float*)d_in[9];
    const float*     lb    = (const float*)d_in[10];
    const float*     hw    = (const float*)d_in[11];
    const float*     hb    = (const float*)d_in[12];
    float* out = (float*)d_out;

    float* x1p; void* xwp;
    cudaGetSymbolAddress((void**)&x1p, g_x1);
    cudaGetSymbolAddress(&xwp, g_xw16);

    // side stream + events, created once
    static cudaStream_t s2 = nullptr;
    static cudaEvent_t evF = nullptr, evJ = nullptr;
    if (s2 == nullptr) {
        cudaStreamCreateWithFlags(&s2, cudaStreamNonBlocking);
        cudaEventCreateWithFlags(&evF, cudaEventDisableTiming);
        cudaEventCreateWithFlags(&evJ, cudaEventDisableTiming);
    }

    // fork: layer-1 conv GEMM is independent of the gate/CSR chain
    cudaEventRecord(evF, 0);
    cudaStreamWaitEvent(s2, evF, 0);
    k_gemm2<128, false, true><<<(NN + 127) / 128, 256, 0, s2>>>(x, cw, nullptr, xwp, NN);
    cudaEventRecord(evJ, s2);

    // main chain: init -> node_pre -> gate -> scan -> fill
    k_init<<<(NN + 255) / 256, 256>>>(ei);
    k_node_pre<<<592, 256>>>(motif, gw1);
    k_edge_gate<<<1184, 256>>>(ei, motif, gw1, gb1, gw2, gb2);
    k_scan1<<<NB_SCAN, 1024>>>();
    k_scan3<<<(NN + 255) / 256, 256>>>();
    k_fill<<<EE / 256, 256>>>();

    // join: agg layer 1 needs xw from side stream
    cudaStreamWaitEvent(0, evJ, 0);
    k_agg<<<(NN + 7) / 8, 256>>>(x, x1p, cb, lg, lb);

    // layer 2 (serial: depends on x1)
    k_gemm2<128, false, true><<<(NN + 127) / 128, 256>>>(x1p, cw + 128 * 128, nullptr, xwp, NN);
    k_agg<<<(NN + 7) / 8, 256>>>(x1p, x1p, cb + 128, lg + 128, lb + 128);

    k_gemm2<64, true, false><<<(NN + 127) / 128, 256>>>(x1p, hw, hb, out, NN);
}

// round 16
// speedup vs baseline: 1.3371x; 1.2275x over previous
#include <cuda_runtime.h>
#include <cuda_fp16.h>
#include <math.h>

#define NN 100000
#define EE 1600000
#define NB_SCAN 98        // ceil(NN/1024)
#define NTILES_G (EE / 128)

typedef unsigned long long u64;

// ---------------- packed f32x2 helpers (Blackwell) ----------------
__device__ __forceinline__ u64 pk2(float lo, float hi) {
    u64 r; asm("mov.b64 %0, {%1, %2};" : "=l"(r) : "f"(lo), "f"(hi)); return r;
}
__device__ __forceinline__ void upk2(u64 v, float& lo, float& hi) {
    asm("mov.b64 {%0, %1}, %2;" : "=f"(lo), "=f"(hi) : "l"(v));
}
__device__ __forceinline__ u64 ffma2(u64 a, u64 b, u64 c) {
    u64 d; asm("fma.rn.f32x2 %0, %1, %2, %3;" : "=l"(d) : "l"(a), "l"(b), "l"(c)); return d;
}

// ---------------- scratch (static device globals; no allocs) ----------------
__device__ __align__(16) float  g_gate[EE];
__device__ __align__(16) int    g_src[EE];
__device__ __align__(16) int    g_dst[EE];
__device__ __align__(16) int    g_off[EE];          // within-bucket offset (from gate atomics)
__device__ __align__(16) u64    g_csr[EE];          // hi: norm bits, lo: src
__device__ __align__(16) float  g_deg[NN];
__device__ __align__(16) float  g_dinv[NN];
__device__ __align__(16) int    g_cnt[NN];
__device__ __align__(16) int    g_tmp[NN];
__device__ __align__(16) int    g_rowptr[NN + 1];
__device__ __align__(16) int    g_bsum[NB_SCAN];
__device__ __align__(16) __half g_tu16[NN * 64];
__device__ __align__(16) __half g_tv16[NN * 64];
__device__ __align__(16) __half g_xw16[NN * 128];
__device__ __align__(16) float  g_x1[NN * 128];
__device__ int g_is32;

// ---------------- init (deg=1 self-loop, cnt=0) + dtype detect ----------------
__global__ void k_init(const long long* __restrict__ ei) {
    int i = blockIdx.x * 256 + threadIdx.x;
    if (i < NN) { g_deg[i] = 1.0f; g_cnt[i] = 0; }
    if (i == 0) {
        int bad = 0;
        for (int t = 0; t < 128; ++t) {
            long long v = ei[t];
            if (v < 0 || v >= (long long)NN) { bad = 1; break; }
        }
        g_is32 = bad;
    }
}

// ---------------- node_pre: warp per node, fp16 output, coalesced stores ----------------
__global__ __launch_bounds__(256) void k_node_pre(const float* __restrict__ motif,
                                                  const float* __restrict__ w1) {
    __shared__ __align__(16) float sW[32 * 64];
    for (int i = threadIdx.x; i < 2048; i += 256) sW[i] = w1[i];
    __syncthreads();

    int lane = threadIdx.x & 31;
    int warpId = (blockIdx.x * 256 + threadIdx.x) >> 5;
    int nWarps = (gridDim.x * 256) >> 5;
    int half = lane >> 4;              // 0: tu (W rows 0..15), 1: tv (rows 16..31)
    int j0 = (lane & 15) * 4;
    const float* wbase = &sW[half * 16 * 64 + j0];

    for (int n = warpId; n < NN; n += nWarps) {
        const float4* m4 = (const float4*)(motif + (size_t)n * 16);
        float m[16];
#pragma unroll
        for (int q = 0; q < 4; ++q) {
            float4 v = m4[q];     // uniform per warp -> broadcast
            m[4*q] = v.x; m[4*q+1] = v.y; m[4*q+2] = v.z; m[4*q+3] = v.w;
        }
        u64 a01 = 0ull, a23 = 0ull;
#pragma unroll
        for (int k = 0; k < 16; ++k) {
            float4 w = *(const float4*)&wbase[k * 64];
            u64 w01 = pk2(w.x, w.y), w23 = pk2(w.z, w.w);
            u64 mk = pk2(m[k], m[k]);
            a01 = ffma2(w01, mk, a01);
            a23 = ffma2(w23, mk, a23);
        }
        float4 o;
        upk2(a01, o.x, o.y); upk2(a23, o.z, o.w);
        __half2 h01 = __floats2half2_rn(o.x, o.y);
        __half2 h23 = __floats2half2_rn(o.z, o.w);
        uint2 st;
        st.x = *(unsigned*)&h01; st.y = *(unsigned*)&h23;
        __half* dst = (half ? g_tv16 : g_tu16) + (size_t)n * 64 + j0;
        *(uint2*)dst = st;     // 16 lanes -> contiguous 128B per half
    }
}

// ---------------- gate MLP: pipelined HFMA2 GEMM, 128 edges/tile ----------------
#define SFS 136   // sF row stride in halves
__global__ __launch_bounds__(256, 4) void k_edge_gate(const long long* __restrict__ ei,
                                                      const float* __restrict__ motif,
                                                      const float* __restrict__ w1,
                                                      const float* __restrict__ b1,
                                                      const float* __restrict__ w2,
                                                      const float* __restrict__ b2) {
    __shared__ __align__(16) __half sW16[32 * 64];       // W1 rows 32..63, [k][j] fp16
    __shared__ __align__(16) __half sF16[2][32 * SFS];   // feats [k][edge] fp16
    __shared__ int sS[2][128];
    __shared__ int sD[2][128];

    int tid = threadIdx.x;
    int tx = tid & 15;        // hidden group (j = tx*4 .. tx*4+3)
    int ty = tid >> 4;        // edge group  (edges ty*8 .. ty*8+7)

    for (int i = tid; i < 2048; i += 256) sW16[i] = __float2half(w1[2048 + i]);

    float b1r[4], w2r[4];
#pragma unroll
    for (int n = 0; n < 4; ++n) { b1r[n] = b1[tx * 4 + n]; w2r[n] = w2[tx * 4 + n]; }
    float b2s = b2[0];
    int is32 = g_is32;
    const int* e32 = (const int*)ei;

    int pr = tid >> 2;          // edge-pair slot 0..63 for gather phase
    int q  = tid & 3;           // quarter of the 16 motif dims

#define GATHER_PAIR(sFdst, s0_, d0_, s1_, d1_)                                          \
    {                                                                                   \
        float4 a0 = *(const float4*)(motif + (size_t)(s0_) * 16 + q * 4);               \
        float4 b0v = *(const float4*)(motif + (size_t)(d0_) * 16 + q * 4);              \
        float4 a1 = *(const float4*)(motif + (size_t)(s1_) * 16 + q * 4);               \
        float4 b1v = *(const float4*)(motif + (size_t)(d1_) * 16 + q * 4);              \
        int k0 = q * 4;                                                                 \
        float d0a[4] = { fabsf(a0.x-b0v.x), fabsf(a0.y-b0v.y), fabsf(a0.z-b0v.z), fabsf(a0.w-b0v.w) }; \
        float d1a[4] = { fabsf(a1.x-b1v.x), fabsf(a1.y-b1v.y), fabsf(a1.z-b1v.z), fabsf(a1.w-b1v.w) }; \
        float p0a[4] = { a0.x*b0v.x, a0.y*b0v.y, a0.z*b0v.z, a0.w*b0v.w };              \
        float p1a[4] = { a1.x*b1v.x, a1.y*b1v.y, a1.z*b1v.z, a1.w*b1v.w };              \
        _Pragma("unroll")                                                               \
        for (int j = 0; j < 4; ++j) {                                                   \
            __half2 dm2 = __floats2half2_rn(d0a[j], d1a[j]);                            \
            __half2 pm2 = __floats2half2_rn(p0a[j], p1a[j]);                            \
            *(__half2*)&(sFdst)[(k0 + j) * SFS + 2 * pr] = dm2;                         \
            *(__half2*)&(sFdst)[(16 + k0 + j) * SFS + 2 * pr] = pm2;                    \
        }                                                                               \
    }

    // ---- preamble gather: first tile into buffer 0 ----
    {
        int e0 = blockIdx.x * 128 + 2 * pr;
        int s0, d0, s1, d1;
        if (is32) { s0 = e32[e0]; d0 = e32[EE + e0]; s1 = e32[e0+1]; d1 = e32[EE + e0+1]; }
        else      { s0 = (int)ei[e0]; d0 = (int)ei[EE + e0]; s1 = (int)ei[e0+1]; d1 = (int)ei[EE + e0+1]; }
        if (q == 0) { sS[0][2*pr] = s0; sD[0][2*pr] = d0; sS[0][2*pr+1] = s1; sD[0][2*pr+1] = d1; }
        GATHER_PAIR(sF16[0], s0, d0, s1, d1);
    }

    int buf = 0;
    for (int tile = blockIdx.x; tile < NTILES_G; tile += gridDim.x) {
        __syncthreads();   // sF[buf]/sS[buf] complete; sF[buf^1] free for writes
        int eBase = tile * 128;
        int nt = tile + gridDim.x;
        bool hasNext = (nt < NTILES_G);

        // ---- prefetch next tile's indices ----
        int pS0 = 0, pD0 = 0, pS1 = 0, pD1 = 0;
        if (hasNext) {
            int e0 = nt * 128 + 2 * pr;
            if (is32) { pS0 = e32[e0]; pD0 = e32[EE + e0]; pS1 = e32[e0+1]; pD1 = e32[EE + e0+1]; }
            else      { pS0 = (int)ei[e0]; pD0 = (int)ei[EE + e0]; pS1 = (int)ei[e0+1]; pD1 = (int)ei[EE + e0+1]; }
            if (q == 0) { sS[buf^1][2*pr] = pS0; sD[buf^1][2*pr] = pD0; sS[buf^1][2*pr+1] = pS1; sD[buf^1][2*pr+1] = pD1; }
        }

        // ---- GEMM: HFMA2, pairs along edges. acch[pair 4][hidden 4] ----
        __half2 acch[4][4];
#pragma unroll
        for (int i = 0; i < 4; ++i)
#pragma unroll
            for (int n = 0; n < 4; ++n) acch[i][n] = __half2half2(__float2half(0.f));

        const __half* sFb = sF16[buf];
#pragma unroll 16
        for (int k = 0; k < 32; ++k) {
            uint4 afq = *(const uint4*)&sFb[k * SFS + ty * 8];      // 4 edge-pairs (broadcast)
            uint2 wfq = *(const uint2*)&sW16[k * 64 + tx * 4];      // 4 hidden halves
            __half2 ap[4] = { *(__half2*)&afq.x, *(__half2*)&afq.y,
                              *(__half2*)&afq.z, *(__half2*)&afq.w };
            __half2 w01 = *(__half2*)&wfq.x, w23 = *(__half2*)&wfq.y;
            __half2 bp[4] = { __low2half2(w01), __high2half2(w01),
                              __low2half2(w23), __high2half2(w23) };
#pragma unroll
            for (int i = 0; i < 4; ++i)
#pragma unroll
                for (int n = 0; n < 4; ++n) acch[i][n] = __hfma2(ap[i], bp[n], acch[i][n]);
        }

        float acc[8][4];
#pragma unroll
        for (int i = 0; i < 4; ++i)
#pragma unroll
            for (int n = 0; n < 4; ++n) {
                float2 f = __half22float2(acch[i][n]);
                acc[2*i][n] = f.x; acc[2*i+1][n] = f.y;
            }

        // ---- epilogue: + tu[s] + tv[d] (fp16) + b1, relu, dot w2, reduce ----
        float gp[8];
#pragma unroll
        for (int i = 0; i < 8; ++i) {
            int sl = sS[buf][ty * 8 + i];
            int dl = sD[buf][ty * 8 + i];
            uint2 tu2 = *(const uint2*)(g_tu16 + (size_t)sl * 64 + tx * 4);
            uint2 tv2 = *(const uint2*)(g_tv16 + (size_t)dl * 64 + tx * 4);
            float2 uA = __half22float2(*(__half2*)&tu2.x);
            float2 uB = __half22float2(*(__half2*)&tu2.y);
            float2 vA = __half22float2(*(__half2*)&tv2.x);
            float2 vB = __half22float2(*(__half2*)&tv2.y);
            float h0 = fmaxf(acc[i][0] + uA.x + vA.x + b1r[0], 0.f);
            float h1 = fmaxf(acc[i][1] + uA.y + vA.y + b1r[1], 0.f);
            float h2 = fmaxf(acc[i][2] + uB.x + vB.x + b1r[2], 0.f);
            float h3 = fmaxf(acc[i][3] + uB.y + vB.y + b1r[3], 0.f);
            gp[i] = h0 * w2r[0] + h1 * w2r[1] + h2 * w2r[2] + h3 * w2r[3];
        }
#pragma unroll
        for (int off = 8; off; off >>= 1)
#pragma unroll
            for (int i = 0; i < 8; ++i)
                gp[i] += __shfl_xor_sync(0xffffffffu, gp[i], off);

        // ---- distributed writeback: lane tx<8 owns edge tx of its half ----
        float myGp = gp[0];
#pragma unroll
        for (int i = 1; i < 8; ++i) if (tx == i) myGp = gp[i];   // predicated selects

        if (tx < 8) {
            int slot = ty * 8 + tx;
            int e = eBase + slot;
            int dl = sD[buf][slot];
            float gate = 1.f / (1.f + __expf(-(myGp + b2s)));
            g_gate[e] = gate;
            g_src[e] = sS[buf][slot];
            g_dst[e] = dl;
            atomicAdd(&g_deg[dl], gate);                 // RED, no return
            g_off[e] = atomicAdd(&g_cnt[dl], 1);         // 1 returning atomic per lane, parallel
        }

        // ---- gather next tile's motif feats ----
        if (hasNext) {
            GATHER_PAIR(sF16[buf ^ 1], pS0, pD0, pS1, pD1);
        }
        buf ^= 1;
    }
#undef GATHER_PAIR
}

// ---------------- prefix scan of counts -> per-block inclusive scan (2 barriers) ----------------
__global__ __launch_bounds__(1024) void k_scan1() {
    __shared__ int warpSums[32];
    int t = threadIdx.x;
    int i = blockIdx.x * 1024 + t;
    int v = (i < NN) ? g_cnt[i] : 0;
    int lane = t & 31, wid = t >> 5;

    int s = v;
#pragma unroll
    for (int off = 1; off < 32; off <<= 1) {
        int x = __shfl_up_sync(0xffffffffu, s, off);
        if (lane >= off) s += x;
    }
    if (lane == 31) warpSums[wid] = s;
    __syncthreads();
    if (wid == 0) {
        int ws = warpSums[lane];
#pragma unroll
        for (int off = 1; off < 32; off <<= 1) {
            int x = __shfl_up_sync(0xffffffffu, ws, off);
            if (lane >= off) ws += x;
        }
        warpSums[lane] = ws;
    }
    __syncthreads();
    int addv = wid ? warpSums[wid - 1] : 0;
    int incl = s + addv;
    if (i < NN) g_tmp[i] = incl;
    if (t == 1023) g_bsum[blockIdx.x] = incl;
}

// scan of block sums per-block in smem + rowptr/dinv
__global__ __launch_bounds__(256) void k_scan3() {
    __shared__ int sh[128];
    int t = threadIdx.x;
    if (t < 128) sh[t] = (t < NB_SCAN) ? g_bsum[t] : 0;
    __syncthreads();
#pragma unroll
    for (int off = 1; off < 128; off <<= 1) {
        int x = (t < 128 && t >= off) ? sh[t - off] : 0;
        __syncthreads();
        if (t < 128) sh[t] += x;
        __syncthreads();
    }
    int i = blockIdx.x * 256 + t;
    if (i >= NN) return;
    int b = i >> 10;
    int off = b ? sh[b - 1] : 0;
    int excl = g_tmp[i] - g_cnt[i] + off;
    g_rowptr[i] = excl;
    g_dinv[i] = rsqrtf(g_deg[i]);
    if (i == 0) g_rowptr[NN] = EE;
}

// ---------------- fill CSR (no atomics: p = rowptr[d] + off[e]) ----------------
__global__ void k_fill() {
    int e = blockIdx.x * 256 + threadIdx.x;
    if (e >= EE) return;
    int s = g_src[e], d = g_dst[e];
    float nrm = g_dinv[s] * g_gate[e] * g_dinv[d];
    int p = g_rowptr[d] + g_off[e];
    g_csr[p] = ((u64)(unsigned)__float_as_int(nrm) << 32) | (unsigned)s;
}

// ---------------- tensor-core GEMM: C[M,BN] = A[M,128] @ B[128,BN] ----------------
// fp32 inputs converted to fp16 in smem; mma.sync m16n8k16 with fp32 accumulation.
template <int BN, bool ADD_BIAS, bool OUT_HALF>
__global__ __launch_bounds__(256) void k_gemmT(const float* __restrict__ A,
                                               const float* __restrict__ B,
                                               const float* __restrict__ bias,
                                               void* __restrict__ Cv, int M) {
    constexpr int KT = 32;
    constexpr int SA = 40;          // As row stride in halves (conflict-free ldmatrix)
    constexpr int SB = BN + 8;      // Bs row stride in halves
    constexpr int WN = BN / 2;      // warp n-extent (4m x 2n warp grid)
    constexpr int NA = WN / 8;      // n8 frags per warp

    __shared__ __align__(16) __half As[128 * SA];
    __shared__ __align__(16) __half Bs[KT * SB];

    int tid = threadIdx.x;
    int wid = tid >> 5, lane = tid & 31;
    int rowBase = blockIdx.x * 128;

    int m0w = (wid >> 1) * 32;
    int n0w = (wid & 1) * WN;

    float acc[2][NA][4];
#pragma unroll
    for (int i = 0; i < 2; ++i)
#pragma unroll
        for (int j = 0; j < NA; ++j)
#pragma unroll
            for (int r = 0; r < 4; ++r) acc[i][j][r] = 0.f;

    for (int k0 = 0; k0 < 128; k0 += KT) {
        // ---- load A tile 128x32 fp32 -> fp16 smem ----
        {
            int r = tid >> 1;
            int ks = (tid & 1) * 16;
            int grow = rowBase + r;
            float4 f0 = make_float4(0.f,0.f,0.f,0.f), f1 = f0, f2 = f0, f3 = f0;
            if (grow < M) {
                const float4* ap = (const float4*)(A + (size_t)grow * 128 + k0 + ks);
                f0 = ap[0]; f1 = ap[1]; f2 = ap[2]; f3 = ap[3];
            }
            __half2* dst = (__half2*)&As[r * SA + ks];
            dst[0] = __floats2half2_rn(f0.x, f0.y); dst[1] = __floats2half2_rn(f0.z, f0.w);
            dst[2] = __floats2half2_rn(f1.x, f1.y); dst[3] = __floats2half2_rn(f1.z, f1.w);
            dst[4] = __floats2half2_rn(f2.x, f2.y); dst[5] = __floats2half2_rn(f2.z, f2.w);
            dst[6] = __floats2half2_rn(f3.x, f3.y); dst[7] = __floats2half2_rn(f3.z, f3.w);
        }
        // ---- load B tile 32xBN fp32 -> fp16 smem ----
        if (BN == 128) {
            int kr = tid >> 3;
            int n0 = (tid & 7) * 16;
            const float4* bp = (const float4*)(B + (size_t)(k0 + kr) * BN + n0);
            float4 f0 = bp[0], f1 = bp[1], f2 = bp[2], f3 = bp[3];
            __half2* dst = (__half2*)&Bs[kr * SB + n0];
            dst[0] = __floats2half2_rn(f0.x, f0.y); dst[1] = __floats2half2_rn(f0.z, f0.w);
            dst[2] = __floats2half2_rn(f1.x, f1.y); dst[3] = __floats2half2_rn(f1.z, f1.w);
            dst[4] = __floats2half2_rn(f2.x, f2.y); dst[5] = __floats2half2_rn(f2.z, f2.w);
            dst[6] = __floats2half2_rn(f3.x, f3.y); dst[7] = __floats2half2_rn(f3.z, f3.w);
        } else {
            int kr = tid >> 3;
            int n0 = (tid & 7) * 8;
            const float4* bp = (const float4*)(B + (size_t)(k0 + kr) * BN + n0);
            float4 f0 = bp[0], f1 = bp[1];
            __half2* dst = (__half2*)&Bs[kr * SB + n0];
            dst[0] = __floats2half2_rn(f0.x, f0.y); dst[1] = __floats2half2_rn(f0.z, f0.w);
            dst[2] = __floats2half2_rn(f1.x, f1.y); dst[3] = __floats2half2_rn(f1.z, f1.w);
        }
        __syncthreads();

#pragma unroll
        for (int kk = 0; kk < KT; kk += 16) {
            unsigned a[2][4];
#pragma unroll
            for (int sm = 0; sm < 2; ++sm) {
                const __half* p = &As[(m0w + sm * 16 + (lane & 15)) * SA + kk + (lane >> 4) * 8];
                unsigned sa = (unsigned)__cvta_generic_to_shared(p);
                asm volatile("ldmatrix.sync.aligned.m8n8.x4.shared.b16 {%0,%1,%2,%3}, [%4];"
                             : "=r"(a[sm][0]), "=r"(a[sm][1]), "=r"(a[sm][2]), "=r"(a[sm][3])
                             : "r"(sa));
            }
            unsigned bf[NA][2];
#pragma unroll
            for (int sn = 0; sn < NA; ++sn) {
                const __half* p = &Bs[(kk + (lane & 15)) * SB + n0w + sn * 8];
                unsigned sa = (unsigned)__cvta_generic_to_shared(p);
                asm volatile("ldmatrix.sync.aligned.m8n8.x2.trans.shared.b16 {%0,%1}, [%2];"
                             : "=r"(bf[sn][0]), "=r"(bf[sn][1])
                             : "r"(sa));
            }
#pragma unroll
            for (int sm = 0; sm < 2; ++sm)
#pragma unroll
                for (int sn = 0; sn < NA; ++sn)
                    asm("mma.sync.aligned.m16n8k16.row.col.f32.f16.f16.f32 "
                        "{%0,%1,%2,%3}, {%4,%5,%6,%7}, {%8,%9}, {%0,%1,%2,%3};"
                        : "+f"(acc[sm][sn][0]), "+f"(acc[sm][sn][1]),
                          "+f"(acc[sm][sn][2]), "+f"(acc[sm][sn][3])
                        : "r"(a[sm][0]), "r"(a[sm][1]), "r"(a[sm][2]), "r"(a[sm][3]),
                          "r"(bf[sn][0]), "r"(bf[sn][1]));
        }
        __syncthreads();
    }

    // ---- epilogue: fragment-direct stores ----
    int rq = lane >> 2, cq = (lane & 3) * 2;
#pragma unroll
    for (int sm = 0; sm < 2; ++sm) {
#pragma unroll
        for (int sn = 0; sn < NA; ++sn) {
            int col = n0w + sn * 8 + cq;
            int r0 = rowBase + m0w + sm * 16 + rq;
            int r1 = r0 + 8;
            float c0 = acc[sm][sn][0], c1 = acc[sm][sn][1];
            float c2 = acc[sm][sn][2], c3 = acc[sm][sn][3];
            if (ADD_BIAS) {
                float bb0 = bias[col], bb1 = bias[col + 1];
                c0 += bb0; c1 += bb1; c2 += bb0; c3 += bb1;
            }
            if (OUT_HALF) {
                __half* C = (__half*)Cv;
                if (r0 < M) *(__half2*)(C + (size_t)r0 * BN + col) = __floats2half2_rn(c0, c1);
                if (r1 < M) *(__half2*)(C + (size_t)r1 * BN + col) = __floats2half2_rn(c2, c3);
            } else {
                float* C = (float*)Cv;
                if (r0 < M) { float2 f; f.x = c0; f.y = c1; *(float2*)(C + (size_t)r0 * BN + col) = f; }
                if (r1 < M) { float2 f; f.x = c2; f.y = c3; *(float2*)(C + (size_t)r1 * BN + col) = f; }
            }
        }
    }
}

// ---------------- fused aggregate (fp16 xw) + bias + LN + relu + residual ----------------
__global__ __launch_bounds__(256) void k_agg(const float* __restrict__ xin,
                                             float* __restrict__ xout,
                                             const float* __restrict__ cb,
                                             const float* __restrict__ lg,
                                             const float* __restrict__ lb) {
    int w = (blockIdx.x * 256 + threadIdx.x) >> 5;
    int lane = threadIdx.x & 31;
    if (w >= NN) return;

    int base = g_rowptr[w], end = g_rowptr[w + 1];
    float di = g_dinv[w];
    float sw = di * di;

    uint2 slf = *(const uint2*)(g_xw16 + (size_t)w * 128 + lane * 4);
    float2 sA = __half22float2(*(__half2*)&slf.x);
    float2 sB = __half22float2(*(__half2*)&slf.y);
    float4 acc = make_float4(sA.x * sw, sA.y * sw, sB.x * sw, sB.y * sw);

    int i = base;
    for (; i + 4 <= end; i += 4) {
        u64 c0 = g_csr[i],   c1 = g_csr[i+1];
        u64 c2 = g_csr[i+2], c3 = g_csr[i+3];
        int   s0 = (int)(unsigned)c0, s1 = (int)(unsigned)c1;
        int   s2 = (int)(unsigned)c2, s3 = (int)(unsigned)c3;
        float n0 = __int_as_float((int)(c0 >> 32));
        float n1 = __int_as_float((int)(c1 >> 32));
        float n2 = __int_as_float((int)(c2 >> 32));
        float n3 = __int_as_float((int)(c3 >> 32));
        uint2 h0 = *(const uint2*)(g_xw16 + (size_t)s0 * 128 + lane * 4);
        uint2 h1 = *(const uint2*)(g_xw16 + (size_t)s1 * 128 + lane * 4);
        uint2 h2 = *(const uint2*)(g_xw16 + (size_t)s2 * 128 + lane * 4);
        uint2 h3 = *(const uint2*)(g_xw16 + (size_t)s3 * 128 + lane * 4);
        float2 a0 = __half22float2(*(__half2*)&h0.x), b0 = __half22float2(*(__half2*)&h0.y);
        float2 a1 = __half22float2(*(__half2*)&h1.x), b1 = __half22float2(*(__half2*)&h1.y);
        float2 a2 = __half22float2(*(__half2*)&h2.x), b2 = __half22float2(*(__half2*)&h2.y);
        float2 a3 = __half22float2(*(__half2*)&h3.x), b3 = __half22float2(*(__half2*)&h3.y);
        acc.x += n0 * a0.x + n1 * a1.x + n2 * a2.x + n3 * a3.x;
        acc.y += n0 * a0.y + n1 * a1.y + n2 * a2.y + n3 * a3.y;
        acc.z += n0 * b0.x + n1 * b1.x + n2 * b2.x + n3 * b3.x;
        acc.w += n0 * b0.y + n1 * b1.y + n2 * b2.y + n3 * b3.y;
    }
    for (; i < end; ++i) {
        u64 c0 = g_csr[i];
        int s0 = (int)(unsigned)c0;
        float n0 = __int_as_float((int)(c0 >> 32));
        uint2 h0 = *(const uint2*)(g_xw16 + (size_t)s0 * 128 + lane * 4);
        float2 a0 = __half22float2(*(__half2*)&h0.x), b0 = __half22float2(*(__half2*)&h0.y);
        acc.x += n0 * a0.x; acc.y += n0 * a0.y;
        acc.z += n0 * b0.x; acc.w += n0 * b0.y;
    }

    float4 b = *(const float4*)(cb + lane * 4);
    acc.x += b.x; acc.y += b.y; acc.z += b.z; acc.w += b.w;

    float ssum = acc.x + acc.y + acc.z + acc.w;
#pragma unroll
    for (int o = 16; o; o >>= 1) ssum += __shfl_xor_sync(0xffffffffu, ssum, o);
    float mean = ssum * 0.0078125f;
    float d0 = acc.x - mean, d1 = acc.y - mean, d2 = acc.z - mean, d3 = acc.w - mean;
    float ss = d0*d0 + d1*d1 + d2*d2 + d3*d3;
#pragma unroll
    for (int o = 16; o; o >>= 1) ss += __shfl_xor_sync(0xffffffffu, ss, o);
    float inv = rsqrtf(ss * 0.0078125f + 1e-5f);

    float4 g = *(const float4*)(lg + lane * 4);
    float4 bb = *(const float4*)(lb + lane * 4);
    float4 xi = *(const float4*)(xin + (size_t)w * 128 + lane * 4);
    float4 o4;
    o4.x = xi.x + fmaxf(d0 * inv * g.x + bb.x, 0.f);
    o4.y = xi.y + fmaxf(d1 * inv * g.y + bb.y, 0.f);
    o4.z = xi.z + fmaxf(d2 * inv * g.z + bb.z, 0.f);
    o4.w = xi.w + fmaxf(d3 * inv * g.w + bb.w, 0.f);
    *(float4*)(xout + (size_t)w * 128 + lane * 4) = o4;
}

// ---------------- orchestration ----------------
extern "C" void kernel_launch(void* const* d_in, const int* in_sizes, int n_in,
                              void* d_out, int out_size) {
    const float*     x     = (const float*)d_in[0];
    const float*     motif = (const float*)d_in[1];
    const long long* ei    = (const long long*)d_in[2];
    const float*     gw1   = (const float*)d_in[3];
    const float*     gb1   = (const float*)d_in[4];
    const float*     gw2   = (const float*)d_in[5];
    const float*     gb2   = (const float*)d_in[6];
    const float*     cw    = (const float*)d_in[7];
    const float*     cb    = (const float*)d_in[8];
    const float*     lg    = (const float*)d_in[9];
    const float*     lb    = (const float*)d_in[10];
    const float*     hw    = (const float*)d_in[11];
    const float*     hb    = (const float*)d_in[12];
    float* out = (float*)d_out;

    float* x1p; void* xwp;
    cudaGetSymbolAddress((void**)&x1p, g_x1);
    cudaGetSymbolAddress(&xwp, g_xw16);

    // side stream + events, created once
    static cudaStream_t s2 = nullptr;
    static cudaEvent_t evF = nullptr, evJ = nullptr;
    if (s2 == nullptr) {
        cudaStreamCreateWithFlags(&s2, cudaStreamNonBlocking);
        cudaEventCreateWithFlags(&evF, cudaEventDisableTiming);
        cudaEventCreateWithFlags(&evJ, cudaEventDisableTiming);
    }

    // fork: layer-1 conv GEMM is independent of the gate/CSR chain
    cudaEventRecord(evF, 0);
    cudaStreamWaitEvent(s2, evF, 0);
    k_gemmT<128, false, true><<<(NN + 127) / 128, 256, 0, s2>>>(x, cw, nullptr, xwp, NN);
    cudaEventRecord(evJ, s2);

    // main chain: init -> node_pre -> gate -> scan -> fill
    k_init<<<(NN + 255) / 256, 256>>>(ei);
    k_node_pre<<<592, 256>>>(motif, gw1);
    k_edge_gate<<<1184, 256>>>(ei, motif, gw1, gb1, gw2, gb2);
    k_scan1<<<NB_SCAN, 1024>>>();
    k_scan3<<<(NN + 255) / 256, 256>>>();
    k_fill<<<EE / 256, 256>>>();

    // join: agg layer 1 needs xw from side stream
    cudaStreamWaitEvent(0, evJ, 0);
    k_agg<<<(NN + 7) / 8, 256>>>(x, x1p, cb, lg, lb);

    // layer 2 (serial: depends on x1)
    k_gemmT<128, false, true><<<(NN + 127) / 128, 256>>>(x1p, cw + 128 * 128, nullptr, xwp, NN);
    k_agg<<<(NN + 7) / 8, 256>>>(x1p, x1p, cb + 128, lg + 128, lb + 128);

    k_gemmT<64, true, false><<<(NN + 127) / 128, 256>>>(x1p, hw, hb, out, NN);
}